// round 1
// baseline (speedup 1.0000x reference)
#include <cuda_runtime.h>
#include <cuda_bf16.h>
#include <math.h>

#define C_CLASSES 512
#define DDIM      1024
#define EPS_F     1e-30f
#define SCALE_F   50.0f
#define MAX_N     65536

// ---------------- scratch (no allocations allowed) ----------------
__device__ float g_sums[C_CLASSES * DDIM];        // class sums
__device__ float g_meansT[DDIM * C_CLASSES];      // transposed means, pre-scaled by SCALE/||mean||
__device__ float g_tinv[MAX_N];                   // 1 / max(||target||, EPS)
__device__ int   g_counts_i[C_CLASSES];
__device__ int   g_cursor[C_CLASSES];
__device__ int   g_offsets[C_CLASSES + 1];
__device__ int   g_idx[MAX_N];                    // row indices bucketed by class

// ---------------- zero counts ----------------
__global__ void zero_kernel() {
    int i = threadIdx.x;
    if (i < C_CLASSES) g_counts_i[i] = 0;
}

// ---------------- histogram of labels ----------------
__global__ void count_kernel(const int* __restrict__ labels, int n) {
    __shared__ int hist[C_CLASSES];
    for (int i = threadIdx.x; i < C_CLASSES; i += blockDim.x) hist[i] = 0;
    __syncthreads();
    for (int i = blockIdx.x * blockDim.x + threadIdx.x; i < n; i += gridDim.x * blockDim.x)
        atomicAdd(&hist[labels[i]], 1);
    __syncthreads();
    for (int i = threadIdx.x; i < C_CLASSES; i += blockDim.x) {
        int v = hist[i];
        if (v) atomicAdd(&g_counts_i[i], v);
    }
}

// ---------------- exclusive scan over 512 counts (single block of 512) ----------------
__global__ void scan_kernel() {
    __shared__ int tmp[C_CLASSES];
    int t = threadIdx.x;
    int v = g_counts_i[t];
    tmp[t] = v;
    __syncthreads();
    for (int off = 1; off < C_CLASSES; off <<= 1) {
        int x = (t >= off) ? tmp[t - off] : 0;
        __syncthreads();
        tmp[t] += x;
        __syncthreads();
    }
    g_offsets[t] = tmp[t] - v;     // exclusive
    g_cursor[t]  = tmp[t] - v;
    if (t == C_CLASSES - 1) g_offsets[C_CLASSES] = tmp[t];
}

// ---------------- scatter row indices into class buckets ----------------
__global__ void scatter_kernel(const int* __restrict__ labels, int n) {
    int i = blockIdx.x * blockDim.x + threadIdx.x;
    if (i < n) {
        int p = atomicAdd(&g_cursor[labels[i]], 1);
        g_idx[p] = i;
    }
}

// ---------------- per-class gather + register accumulation (no atomics) ----------------
// grid: (C_CLASSES, DDIM/256), block: 256 threads; thread owns one column.
__global__ void classsum_kernel(const float* __restrict__ ctx) {
    const int c    = blockIdx.x;
    const int col  = blockIdx.y * 256 + threadIdx.x;
    const int beg  = g_offsets[c];
    const int end  = g_offsets[c + 1];

    float a0 = 0.f, a1 = 0.f, a2 = 0.f, a3 = 0.f;
    int i = beg;
    for (; i + 3 < end; i += 4) {
        int r0 = g_idx[i], r1 = g_idx[i + 1], r2 = g_idx[i + 2], r3 = g_idx[i + 3];
        a0 += ctx[(size_t)r0 * DDIM + col];
        a1 += ctx[(size_t)r1 * DDIM + col];
        a2 += ctx[(size_t)r2 * DDIM + col];
        a3 += ctx[(size_t)r3 * DDIM + col];
    }
    for (; i < end; i++) a0 += ctx[(size_t)g_idx[i] * DDIM + col];
    g_sums[(size_t)c * DDIM + col] = (a0 + a1) + (a2 + a3);
}

// ---------------- finalize: means -> d_out, scaled transposed means -> g_meansT ----------------
// grid: C_CLASSES blocks of 256
__global__ void finalize_kernel(float* __restrict__ means_out) {
    const int c   = blockIdx.x;
    const int tid = threadIdx.x;
    const float inv = 1.f / fmaxf((float)g_counts_i[c], 1.f);

    float m[4];
    float ss = 0.f;
#pragma unroll
    for (int j = 0; j < 4; j++) {
        int d = tid + 256 * j;
        float v = g_sums[(size_t)c * DDIM + d] * inv;
        m[j] = v;
        means_out[(size_t)c * DDIM + d] = v;
        ss += v * v;
    }
    // block reduce ss
    __shared__ float red[8];
#pragma unroll
    for (int o = 16; o > 0; o >>= 1) ss += __shfl_xor_sync(0xffffffffu, ss, o);
    if ((tid & 31) == 0) red[tid >> 5] = ss;
    __syncthreads();
    __shared__ float s_scale;
    if (tid == 0) {
        float tot = 0.f;
#pragma unroll
        for (int k = 0; k < 8; k++) tot += red[k];
        s_scale = SCALE_F / fmaxf(sqrtf(tot), EPS_F);
    }
    __syncthreads();
    const float sc = s_scale;
#pragma unroll
    for (int j = 0; j < 4; j++) {
        int d = tid + 256 * j;
        g_meansT[(size_t)d * C_CLASSES + c] = m[j] * sc;
    }
}

// ---------------- target inverse norms; one warp per row ----------------
__global__ void tinv_kernel(const float4* __restrict__ tgt4, int n_tgt) {
    int warp = (blockIdx.x * blockDim.x + threadIdx.x) >> 5;
    int lane = threadIdx.x & 31;
    if (warp >= n_tgt) return;
    const float4* row = tgt4 + (size_t)warp * (DDIM / 4);
    float ss = 0.f;
#pragma unroll
    for (int j = 0; j < 8; j++) {
        float4 v = row[lane + 32 * j];
        ss += v.x * v.x + v.y * v.y + v.z * v.z + v.w * v.w;
    }
#pragma unroll
    for (int o = 16; o > 0; o >>= 1) ss += __shfl_xor_sync(0xffffffffu, ss, o);
    if (lane == 0) g_tinv[warp] = 1.f / fmaxf(sqrtf(ss), EPS_F);
}

// ---------------- fp32 SIMT GEMM: C[M,512] = A[M,1024] * g_meansT[1024,512], *g_tinv[m] ----------------
#define BM 128
#define BN 128
#define BK 16
#define AS_STRIDE (BM + 4)

__global__ __launch_bounds__(256) void gemm_kernel(const float* __restrict__ A,
                                                   float* __restrict__ Cout) {
    __shared__ float As[BK * AS_STRIDE];   // As[k][m], padded
    __shared__ float Bs[BK * BN];          // Bs[k][n]

    const int m0  = blockIdx.y * BM;
    const int n0  = blockIdx.x * BN;
    const int tid = threadIdx.x;

    // A load map: 4 threads per row, each a float4
    const int arow = tid >> 2;          // 0..63
    const int ak4  = (tid & 3) * 4;     // 0,4,8,12
    // B load map: 32 threads per k-row, each a float4
    const int bk   = tid >> 5;          // 0..7
    const int bn4  = (tid & 31) * 4;

    const int ty = tid >> 4;            // 0..15
    const int tx = tid & 15;            // 0..15

    float acc[8][8];
#pragma unroll
    for (int i = 0; i < 8; i++)
#pragma unroll
        for (int j = 0; j < 8; j++) acc[i][j] = 0.f;

    for (int k0 = 0; k0 < DDIM; k0 += BK) {
#pragma unroll
        for (int p = 0; p < 2; p++) {
            int mr = arow + p * 64;
            float4 a = *(const float4*)&A[(size_t)(m0 + mr) * DDIM + k0 + ak4];
            As[(ak4 + 0) * AS_STRIDE + mr] = a.x;
            As[(ak4 + 1) * AS_STRIDE + mr] = a.y;
            As[(ak4 + 2) * AS_STRIDE + mr] = a.z;
            As[(ak4 + 3) * AS_STRIDE + mr] = a.w;
        }
#pragma unroll
        for (int p = 0; p < 2; p++) {
            int kr = bk + p * 8;
            *(float4*)&Bs[kr * BN + bn4] =
                *(const float4*)&g_meansT[(size_t)(k0 + kr) * C_CLASSES + n0 + bn4];
        }
        __syncthreads();

#pragma unroll
        for (int kk = 0; kk < BK; kk++) {
            float a[8], b[8];
            *(float4*)&a[0] = *(const float4*)&As[kk * AS_STRIDE + ty * 8];
            *(float4*)&a[4] = *(const float4*)&As[kk * AS_STRIDE + ty * 8 + 4];
            *(float4*)&b[0] = *(const float4*)&Bs[kk * BN + tx * 8];
            *(float4*)&b[4] = *(const float4*)&Bs[kk * BN + tx * 8 + 4];
#pragma unroll
            for (int i = 0; i < 8; i++)
#pragma unroll
                for (int j = 0; j < 8; j++) acc[i][j] += a[i] * b[j];
        }
        __syncthreads();
    }

#pragma unroll
    for (int i = 0; i < 8; i++) {
        int m = m0 + ty * 8 + i;
        float t = g_tinv[m];
#pragma unroll
        for (int j = 0; j < 8; j += 4) {
            float4 o;
            o.x = acc[i][j + 0] * t;
            o.y = acc[i][j + 1] * t;
            o.z = acc[i][j + 2] * t;
            o.w = acc[i][j + 3] * t;
            *(float4*)&Cout[(size_t)m * C_CLASSES + n0 + tx * 8 + j] = o;
        }
    }
}

// ---------------- launch ----------------
extern "C" void kernel_launch(void* const* d_in, const int* in_sizes, int n_in,
                              void* d_out, int out_size) {
    const float* ctx    = (const float*)d_in[0];
    const int*   labels = (const int*)d_in[1];
    const float* tgt    = (const float*)d_in[2];
    const int n_ctx = in_sizes[1];
    const int n_tgt = in_sizes[2] / DDIM;

    float* logits    = (float*)d_out;                                  // [n_tgt, 512]
    float* means_out = (float*)d_out + (size_t)n_tgt * C_CLASSES;      // [512, 1024]

    zero_kernel<<<1, C_CLASSES>>>();
    count_kernel<<<64, 256>>>(labels, n_ctx);
    scan_kernel<<<1, C_CLASSES>>>();
    scatter_kernel<<<(n_ctx + 255) / 256, 256>>>(labels, n_ctx);
    classsum_kernel<<<dim3(C_CLASSES, DDIM / 256), 256>>>(ctx);
    finalize_kernel<<<C_CLASSES, 256>>>(means_out);
    tinv_kernel<<<(n_tgt + 7) / 8, 256>>>((const float4*)tgt, n_tgt);
    gemm_kernel<<<dim3(C_CLASSES / BN, n_tgt / BM), 256>>>(tgt, logits);
}

// round 3
// speedup vs baseline: 2.3281x; 2.3281x over previous
#include <cuda_runtime.h>
#include <cuda_bf16.h>
#include <math.h>
#include <stdint.h>

#define C_CLASSES 512
#define DDIM      1024
#define EPS_F     1e-30f
#define SCALE_F   50.0f
#define MAX_N     65536

// ---------------- scratch (device globals; no allocations allowed) ----------------
__device__ float         g_sums[C_CLASSES * DDIM];
__device__ __nv_bfloat16 g_bhi[C_CLASSES * DDIM];   // scaled means, hi bf16, [N][K]
__device__ __nv_bfloat16 g_blo[C_CLASSES * DDIM];   // scaled means, lo bf16, [N][K]
__device__ __nv_bfloat16 g_ahi[(size_t)MAX_N * DDIM];
__device__ __nv_bfloat16 g_alo[(size_t)MAX_N * DDIM];
__device__ float         g_tinv[MAX_N];
__device__ int           g_counts_i[C_CLASSES];
__device__ int           g_cursor[C_CLASSES];
__device__ int           g_offsets[C_CLASSES + 1];
__device__ int           g_idx[MAX_N];

// ---------------- PTX helpers (sm_80+ baseline features only; nothing 'a'-gated) ----
__device__ __forceinline__ uint32_t smem_u32(const void* p) {
    uint32_t a;
    asm("{ .reg .u64 t; cvta.to.shared.u64 t, %1; cvt.u32.u64 %0, t; }" : "=r"(a) : "l"(p));
    return a;
}
#define CP_ASYNC16(dst, src) \
    asm volatile("cp.async.cg.shared.global [%0], [%1], 16;" :: "r"((uint32_t)(dst)), "l"(src))
#define CP_COMMIT() asm volatile("cp.async.commit_group;" ::: "memory")
#define CP_WAIT(n)  asm volatile("cp.async.wait_group %0;" :: "n"(n) : "memory")

__device__ __forceinline__ void ldsm_x4(uint32_t* r, uint32_t addr) {
    asm volatile("ldmatrix.sync.aligned.m8n8.x4.shared.b16 {%0,%1,%2,%3}, [%4];"
                 : "=r"(r[0]), "=r"(r[1]), "=r"(r[2]), "=r"(r[3]) : "r"(addr));
}
__device__ __forceinline__ void mma16816(float* c, const uint32_t* a, const uint32_t* b) {
    asm volatile("mma.sync.aligned.m16n8k16.row.col.f32.bf16.bf16.f32 "
                 "{%0,%1,%2,%3}, {%4,%5,%6,%7}, {%8,%9}, {%0,%1,%2,%3};"
                 : "+f"(c[0]), "+f"(c[1]), "+f"(c[2]), "+f"(c[3])
                 : "r"(a[0]), "r"(a[1]), "r"(a[2]), "r"(a[3]), "r"(b[0]), "r"(b[1]));
}
// 128B-row XOR swizzle: 16B column index c ^= (row & 7)
#define SWZ(o) ((o) ^ (((o) >> 3) & 0x70))

// ---------------- zero counts ----------------
__global__ void zero_kernel() {
    int i = threadIdx.x;
    if (i < C_CLASSES) g_counts_i[i] = 0;
}

// ---------------- histogram of labels ----------------
__global__ void count_kernel(const int* __restrict__ labels, int n) {
    __shared__ int hist[C_CLASSES];
    for (int i = threadIdx.x; i < C_CLASSES; i += blockDim.x) hist[i] = 0;
    __syncthreads();
    for (int i = blockIdx.x * blockDim.x + threadIdx.x; i < n; i += gridDim.x * blockDim.x)
        atomicAdd(&hist[labels[i]], 1);
    __syncthreads();
    for (int i = threadIdx.x; i < C_CLASSES; i += blockDim.x) {
        int v = hist[i];
        if (v) atomicAdd(&g_counts_i[i], v);
    }
}

// ---------------- exclusive scan over 512 counts ----------------
__global__ void scan_kernel() {
    __shared__ int tmp[C_CLASSES];
    int t = threadIdx.x;
    int v = g_counts_i[t];
    tmp[t] = v;
    __syncthreads();
    for (int off = 1; off < C_CLASSES; off <<= 1) {
        int x = (t >= off) ? tmp[t - off] : 0;
        __syncthreads();
        tmp[t] += x;
        __syncthreads();
    }
    g_offsets[t] = tmp[t] - v;
    g_cursor[t]  = tmp[t] - v;
    if (t == C_CLASSES - 1) g_offsets[C_CLASSES] = tmp[t];
}

// ---------------- scatter row indices into class buckets ----------------
__global__ void scatter_kernel(const int* __restrict__ labels, int n) {
    int i = blockIdx.x * blockDim.x + threadIdx.x;
    if (i < n) {
        int p = atomicAdd(&g_cursor[labels[i]], 1);
        g_idx[p] = i;
    }
}

// ---------------- per-class gather + register accumulation ----------------
__global__ void classsum_kernel(const float* __restrict__ ctx) {
    const int c   = blockIdx.x;
    const int col = blockIdx.y * 256 + threadIdx.x;
    const int beg = g_offsets[c];
    const int end = g_offsets[c + 1];

    float a0 = 0.f, a1 = 0.f, a2 = 0.f, a3 = 0.f;
    int i = beg;
    for (; i + 3 < end; i += 4) {
        int r0 = g_idx[i], r1 = g_idx[i + 1], r2 = g_idx[i + 2], r3 = g_idx[i + 3];
        a0 += ctx[(size_t)r0 * DDIM + col];
        a1 += ctx[(size_t)r1 * DDIM + col];
        a2 += ctx[(size_t)r2 * DDIM + col];
        a3 += ctx[(size_t)r3 * DDIM + col];
    }
    for (; i < end; i++) a0 += ctx[(size_t)g_idx[i] * DDIM + col];
    g_sums[(size_t)c * DDIM + col] = (a0 + a1) + (a2 + a3);
}

// ---------------- finalize: means -> d_out; scaled bf16 hi/lo B -> g_bhi/g_blo ----------------
__global__ void finalize_kernel(float* __restrict__ means_out) {
    const int c   = blockIdx.x;
    const int tid = threadIdx.x;
    const float inv = 1.f / fmaxf((float)g_counts_i[c], 1.f);

    float m[4];
    float ss = 0.f;
#pragma unroll
    for (int j = 0; j < 4; j++) {
        int d = tid + 256 * j;
        float v = g_sums[(size_t)c * DDIM + d] * inv;
        m[j] = v;
        means_out[(size_t)c * DDIM + d] = v;
        ss += v * v;
    }
    __shared__ float red[8];
#pragma unroll
    for (int o = 16; o > 0; o >>= 1) ss += __shfl_xor_sync(0xffffffffu, ss, o);
    if ((tid & 31) == 0) red[tid >> 5] = ss;
    __syncthreads();
    __shared__ float s_scale;
    if (tid == 0) {
        float tot = 0.f;
#pragma unroll
        for (int k = 0; k < 8; k++) tot += red[k];
        s_scale = SCALE_F / fmaxf(sqrtf(tot), EPS_F);
    }
    __syncthreads();
    const float sc = s_scale;
#pragma unroll
    for (int j = 0; j < 4; j++) {
        int d = tid + 256 * j;
        float s = m[j] * sc;
        __nv_bfloat16 h = __float2bfloat16_rn(s);
        g_bhi[(size_t)c * DDIM + d] = h;
        g_blo[(size_t)c * DDIM + d] = __float2bfloat16_rn(s - __bfloat162float(h));
    }
}

// ---------------- fused: target bf16 hi/lo split + inverse norms (one warp per row) ----------------
__global__ void split_tinv_kernel(const float4* __restrict__ tgt4, int n_tgt) {
    int w    = (blockIdx.x * blockDim.x + threadIdx.x) >> 5;
    int lane = threadIdx.x & 31;
    if (w >= n_tgt) return;
    const float4* row = tgt4 + (size_t)w * (DDIM / 4);
    uint2* hrow = (uint2*)(g_ahi + (size_t)w * DDIM);
    uint2* lrow = (uint2*)(g_alo + (size_t)w * DDIM);
    float ss = 0.f;
#pragma unroll
    for (int j = 0; j < 8; j++) {
        int e4 = lane + 32 * j;
        float4 v = row[e4];
        ss += v.x * v.x + v.y * v.y + v.z * v.z + v.w * v.w;
        __nv_bfloat162 h0 = __floats2bfloat162_rn(v.x, v.y);
        __nv_bfloat162 h1 = __floats2bfloat162_rn(v.z, v.w);
        float2 f0 = __bfloat1622float2(h0);
        float2 f1 = __bfloat1622float2(h1);
        __nv_bfloat162 l0 = __floats2bfloat162_rn(v.x - f0.x, v.y - f0.y);
        __nv_bfloat162 l1 = __floats2bfloat162_rn(v.z - f1.x, v.w - f1.y);
        uint2 hu, lu;
        hu.x = *reinterpret_cast<uint32_t*>(&h0);
        hu.y = *reinterpret_cast<uint32_t*>(&h1);
        lu.x = *reinterpret_cast<uint32_t*>(&l0);
        lu.y = *reinterpret_cast<uint32_t*>(&l1);
        hrow[e4] = hu;
        lrow[e4] = lu;
    }
#pragma unroll
    for (int o = 16; o > 0; o >>= 1) ss += __shfl_xor_sync(0xffffffffu, ss, o);
    if (lane == 0) g_tinv[w] = 1.f / fmaxf(sqrtf(ss), EPS_F);
}

// ---------------- bf16x3 HMMA GEMM: out[M,512] = (Ahi+Alo)(Bhi+Blo)^T * tinv ----------------
// CTA tile 128x128, 8 warps (4 m x 2 n), warp tile 32x64, K-chunk 64, double buffer.
#define MT   128
#define NT   128
#define KC   64
#define NC   (DDIM / KC)             // 16
#define OFF_AHI  0
#define OFF_ALO  16384
#define OFF_BHI  32768
#define OFF_BLO  49152
#define STAGE    65536
#define SMEM_BYTES (2 * STAGE + 1024)

__device__ __forceinline__ void load_chunk(uint32_t stage, int m0, int n0, int gk0, int tid) {
#pragma unroll
    for (int p = 0; p < 4; p++) {
        int i = tid + p * 256;
        int row = i >> 3, c16 = i & 7;
        uint32_t off = SWZ((uint32_t)row * 128 + (uint32_t)c16 * 16);
        const char* sh = (const char*)(g_ahi + (size_t)(m0 + row) * DDIM + gk0) + c16 * 16;
        const char* sl = (const char*)(g_alo + (size_t)(m0 + row) * DDIM + gk0) + c16 * 16;
        CP_ASYNC16(stage + OFF_AHI + off, sh);
        CP_ASYNC16(stage + OFF_ALO + off, sl);
    }
#pragma unroll
    for (int p = 0; p < 4; p++) {
        int i = tid + p * 256;
        int row = i >> 3, c16 = i & 7;
        uint32_t off = SWZ((uint32_t)row * 128 + (uint32_t)c16 * 16);
        const char* sh = (const char*)(g_bhi + (size_t)(n0 + row) * DDIM + gk0) + c16 * 16;
        const char* sl = (const char*)(g_blo + (size_t)(n0 + row) * DDIM + gk0) + c16 * 16;
        CP_ASYNC16(stage + OFF_BHI + off, sh);
        CP_ASYNC16(stage + OFF_BLO + off, sl);
    }
    CP_COMMIT();
}

__global__ void __launch_bounds__(256, 1) gemm_mma_kernel(float* __restrict__ out) {
    extern __shared__ char dsm[];
    uint32_t sb = (smem_u32(dsm) + 1023) & ~1023u;

    const int tid  = threadIdx.x;
    const int wid  = tid >> 5;
    const int lane = tid & 31;
    const int wm   = wid >> 1;            // 0..3 (m)
    const int wn   = wid & 1;             // 0..1 (n)
    const int n0 = blockIdx.x * NT;
    const int m0 = blockIdx.y * MT;

    float acc[2][8][4];
#pragma unroll
    for (int a = 0; a < 2; a++)
#pragma unroll
        for (int b = 0; b < 8; b++)
#pragma unroll
            for (int c = 0; c < 4; c++) acc[a][b][c] = 0.f;

    // prologue
    load_chunk(sb, m0, n0, 0, tid);
    load_chunk(sb + STAGE, m0, n0, KC, tid);

    // precomputed lane pieces
    const int a_r  = (lane & 15);             // row within 16
    const int a_kh = (lane >> 4);             // k half
    const int b_r  = (lane & 7) + ((lane >> 4) << 3);
    const int b_kh = (lane >> 3) & 1;

    for (int c = 0; c < NC; c++) {
        if (c < NC - 2) CP_WAIT(1); else CP_WAIT(0);
        __syncthreads();
        uint32_t stage = sb + (uint32_t)(c & 1) * STAGE;

#pragma unroll
        for (int k16 = 0; k16 < 4; k16++) {
            uint32_t ah[2][4], al[2][4], bh[4][4], bl[4][4];
#pragma unroll
            for (int mt = 0; mt < 2; mt++) {
                int row = wm * 32 + mt * 16 + a_r;
                uint32_t c16 = (uint32_t)((k16 * 2 + a_kh) ^ (row & 7));
                uint32_t off = (uint32_t)row * 128 + c16 * 16;
                ldsm_x4(ah[mt], stage + OFF_AHI + off);
                ldsm_x4(al[mt], stage + OFF_ALO + off);
            }
#pragma unroll
            for (int nt = 0; nt < 4; nt++) {
                int row = wn * 64 + nt * 16 + b_r;
                uint32_t c16 = (uint32_t)((k16 * 2 + b_kh) ^ (row & 7));
                uint32_t off = (uint32_t)row * 128 + c16 * 16;
                ldsm_x4(bh[nt], stage + OFF_BHI + off);
                ldsm_x4(bl[nt], stage + OFF_BLO + off);
            }
#pragma unroll
            for (int mt = 0; mt < 2; mt++) {
#pragma unroll
                for (int nt = 0; nt < 4; nt++) {
                    mma16816(acc[mt][nt * 2 + 0], ah[mt], &bh[nt][0]);
                    mma16816(acc[mt][nt * 2 + 1], ah[mt], &bh[nt][2]);
                    mma16816(acc[mt][nt * 2 + 0], al[mt], &bh[nt][0]);
                    mma16816(acc[mt][nt * 2 + 1], al[mt], &bh[nt][2]);
                    mma16816(acc[mt][nt * 2 + 0], ah[mt], &bl[nt][0]);
                    mma16816(acc[mt][nt * 2 + 1], ah[mt], &bl[nt][2]);
                }
            }
        }
        __syncthreads();
        if (c + 2 < NC) load_chunk(stage, m0, n0, (c + 2) * KC, tid);
    }

    // epilogue: scale by 1/||t|| and store
    const int qrow = lane >> 2;
    const int qcol = (lane & 3) * 2;
#pragma unroll
    for (int mt = 0; mt < 2; mt++) {
        int r0 = m0 + wm * 32 + mt * 16 + qrow;
        int r1 = r0 + 8;
        float t0 = g_tinv[r0], t1 = g_tinv[r1];
        float* p0 = out + (size_t)r0 * C_CLASSES + n0 + wn * 64 + qcol;
        float* p1 = out + (size_t)r1 * C_CLASSES + n0 + wn * 64 + qcol;
#pragma unroll
        for (int nf = 0; nf < 8; nf++) {
            float2 v0, v1;
            v0.x = acc[mt][nf][0] * t0; v0.y = acc[mt][nf][1] * t0;
            v1.x = acc[mt][nf][2] * t1; v1.y = acc[mt][nf][3] * t1;
            *(float2*)(p0 + nf * 8) = v0;
            *(float2*)(p1 + nf * 8) = v1;
        }
    }
}

// ---------------- launch ----------------
extern "C" void kernel_launch(void* const* d_in, const int* in_sizes, int n_in,
                              void* d_out, int out_size) {
    const float* ctx    = (const float*)d_in[0];
    const int*   labels = (const int*)d_in[1];
    const float* tgt    = (const float*)d_in[2];
    const int n_ctx = in_sizes[1];
    const int n_tgt = in_sizes[2] / DDIM;

    float* logits    = (float*)d_out;
    float* means_out = (float*)d_out + (size_t)n_tgt * C_CLASSES;

    cudaFuncSetAttribute(gemm_mma_kernel, cudaFuncAttributeMaxDynamicSharedMemorySize, SMEM_BYTES);

    zero_kernel<<<1, C_CLASSES>>>();
    count_kernel<<<64, 256>>>(labels, n_ctx);
    scan_kernel<<<1, C_CLASSES>>>();
    scatter_kernel<<<(n_ctx + 255) / 256, 256>>>(labels, n_ctx);
    classsum_kernel<<<dim3(C_CLASSES, DDIM / 256), 256>>>(ctx);
    finalize_kernel<<<C_CLASSES, 256>>>(means_out);
    split_tinv_kernel<<<(n_tgt + 7) / 8, 256>>>((const float4*)tgt, n_tgt);
    gemm_mma_kernel<<<dim3(C_CLASSES / NT, n_tgt / MT), 256, SMEM_BYTES>>>(logits);
}

// round 4
// speedup vs baseline: 2.4892x; 1.0692x over previous
#include <cuda_runtime.h>
#include <cuda_bf16.h>
#include <math.h>
#include <stdint.h>

#define C_CLASSES 512
#define DDIM      1024
#define EPS_F     1e-30f
#define SCALE_F   50.0f
#define MAX_N     65536

// ---------------- scratch (device globals; no allocations allowed) ----------------
__device__ float         g_sums[C_CLASSES * DDIM];
__device__ __nv_bfloat16 g_bhi[C_CLASSES * DDIM];   // scaled means, hi bf16, [N][K]
__device__ __nv_bfloat16 g_blo[C_CLASSES * DDIM];   // scaled means, lo bf16, [N][K]
__device__ __nv_bfloat16 g_ahi[(size_t)MAX_N * DDIM];
__device__ __nv_bfloat16 g_alo[(size_t)MAX_N * DDIM];
__device__ float         g_tinv[MAX_N];
__device__ int           g_counts_i[C_CLASSES];
__device__ int           g_cursor[C_CLASSES];
__device__ int           g_offsets[C_CLASSES + 1];
__device__ int           g_idx[MAX_N];

// ---------------- PTX helpers (sm_80+ baseline features only) ----------------
__device__ __forceinline__ uint32_t smem_u32(const void* p) {
    uint32_t a;
    asm("{ .reg .u64 t; cvta.to.shared.u64 t, %1; cvt.u32.u64 %0, t; }" : "=r"(a) : "l"(p));
    return a;
}
#define CP_ASYNC16(dst, src) \
    asm volatile("cp.async.cg.shared.global [%0], [%1], 16;" :: "r"((uint32_t)(dst)), "l"(src))
#define CP_COMMIT() asm volatile("cp.async.commit_group;" ::: "memory")
#define CP_WAIT(n)  asm volatile("cp.async.wait_group %0;" :: "n"(n) : "memory")

__device__ __forceinline__ void ldsm_x4(uint32_t* r, uint32_t addr) {
    asm volatile("ldmatrix.sync.aligned.m8n8.x4.shared.b16 {%0,%1,%2,%3}, [%4];"
                 : "=r"(r[0]), "=r"(r[1]), "=r"(r[2]), "=r"(r[3]) : "r"(addr));
}
__device__ __forceinline__ void mma16816(float* c, const uint32_t* a, const uint32_t* b) {
    asm volatile("mma.sync.aligned.m16n8k16.row.col.f32.bf16.bf16.f32 "
                 "{%0,%1,%2,%3}, {%4,%5,%6,%7}, {%8,%9}, {%0,%1,%2,%3};"
                 : "+f"(c[0]), "+f"(c[1]), "+f"(c[2]), "+f"(c[3])
                 : "r"(a[0]), "r"(a[1]), "r"(a[2]), "r"(a[3]), "r"(b[0]), "r"(b[1]));
}
// 128B-row XOR swizzle: 16B column index c ^= (row & 7)
#define SWZ(o) ((o) ^ (((o) >> 3) & 0x70))

// ---------------- zero counts ----------------
__global__ void zero_kernel() {
    int i = threadIdx.x;
    if (i < C_CLASSES) g_counts_i[i] = 0;
}

// ---------------- histogram of labels ----------------
__global__ void count_kernel(const int* __restrict__ labels, int n) {
    __shared__ int hist[C_CLASSES];
    for (int i = threadIdx.x; i < C_CLASSES; i += blockDim.x) hist[i] = 0;
    __syncthreads();
    for (int i = blockIdx.x * blockDim.x + threadIdx.x; i < n; i += gridDim.x * blockDim.x)
        atomicAdd(&hist[labels[i]], 1);
    __syncthreads();
    for (int i = threadIdx.x; i < C_CLASSES; i += blockDim.x) {
        int v = hist[i];
        if (v) atomicAdd(&g_counts_i[i], v);
    }
}

// ---------------- exclusive scan over 512 counts ----------------
__global__ void scan_kernel() {
    __shared__ int tmp[C_CLASSES];
    int t = threadIdx.x;
    int v = g_counts_i[t];
    tmp[t] = v;
    __syncthreads();
    for (int off = 1; off < C_CLASSES; off <<= 1) {
        int x = (t >= off) ? tmp[t - off] : 0;
        __syncthreads();
        tmp[t] += x;
        __syncthreads();
    }
    g_offsets[t] = tmp[t] - v;
    g_cursor[t]  = tmp[t] - v;
    if (t == C_CLASSES - 1) g_offsets[C_CLASSES] = tmp[t];
}

// ---------------- scatter row indices into class buckets ----------------
__global__ void scatter_kernel(const int* __restrict__ labels, int n) {
    int i = blockIdx.x * blockDim.x + threadIdx.x;
    if (i < n) {
        int p = atomicAdd(&g_cursor[labels[i]], 1);
        g_idx[p] = i;
    }
}

// ---------------- per-class gather + register accumulation ----------------
__global__ void classsum_kernel(const float* __restrict__ ctx) {
    const int c   = blockIdx.x;
    const int col = blockIdx.y * 256 + threadIdx.x;
    const int beg = g_offsets[c];
    const int end = g_offsets[c + 1];

    float a0 = 0.f, a1 = 0.f, a2 = 0.f, a3 = 0.f;
    int i = beg;
    for (; i + 3 < end; i += 4) {
        int r0 = g_idx[i], r1 = g_idx[i + 1], r2 = g_idx[i + 2], r3 = g_idx[i + 3];
        a0 += ctx[(size_t)r0 * DDIM + col];
        a1 += ctx[(size_t)r1 * DDIM + col];
        a2 += ctx[(size_t)r2 * DDIM + col];
        a3 += ctx[(size_t)r3 * DDIM + col];
    }
    for (; i < end; i++) a0 += ctx[(size_t)g_idx[i] * DDIM + col];
    g_sums[(size_t)c * DDIM + col] = (a0 + a1) + (a2 + a3);
}

// ---------------- finalize: means -> d_out; scaled bf16 hi/lo B -> g_bhi/g_blo ----------------
__global__ void finalize_kernel(float* __restrict__ means_out) {
    const int c   = blockIdx.x;
    const int tid = threadIdx.x;
    const float inv = 1.f / fmaxf((float)g_counts_i[c], 1.f);

    float m[4];
    float ss = 0.f;
#pragma unroll
    for (int j = 0; j < 4; j++) {
        int d = tid + 256 * j;
        float v = g_sums[(size_t)c * DDIM + d] * inv;
        m[j] = v;
        means_out[(size_t)c * DDIM + d] = v;
        ss += v * v;
    }
    __shared__ float red[8];
#pragma unroll
    for (int o = 16; o > 0; o >>= 1) ss += __shfl_xor_sync(0xffffffffu, ss, o);
    if ((tid & 31) == 0) red[tid >> 5] = ss;
    __syncthreads();
    __shared__ float s_scale;
    if (tid == 0) {
        float tot = 0.f;
#pragma unroll
        for (int k = 0; k < 8; k++) tot += red[k];
        s_scale = SCALE_F / fmaxf(sqrtf(tot), EPS_F);
    }
    __syncthreads();
    const float sc = s_scale;
#pragma unroll
    for (int j = 0; j < 4; j++) {
        int d = tid + 256 * j;
        float s = m[j] * sc;
        __nv_bfloat16 h = __float2bfloat16_rn(s);
        g_bhi[(size_t)c * DDIM + d] = h;
        g_blo[(size_t)c * DDIM + d] = __float2bfloat16_rn(s - __bfloat162float(h));
    }
}

// ---------------- fused: target bf16 hi/lo split + inverse norms (one warp per row) ----------------
__global__ void split_tinv_kernel(const float4* __restrict__ tgt4, int n_tgt) {
    int w    = (blockIdx.x * blockDim.x + threadIdx.x) >> 5;
    int lane = threadIdx.x & 31;
    if (w >= n_tgt) return;
    const float4* row = tgt4 + (size_t)w * (DDIM / 4);
    uint2* hrow = (uint2*)(g_ahi + (size_t)w * DDIM);
    uint2* lrow = (uint2*)(g_alo + (size_t)w * DDIM);
    float ss = 0.f;
#pragma unroll
    for (int j = 0; j < 8; j++) {
        int e4 = lane + 32 * j;
        float4 v = row[e4];
        ss += v.x * v.x + v.y * v.y + v.z * v.z + v.w * v.w;
        __nv_bfloat162 h0 = __floats2bfloat162_rn(v.x, v.y);
        __nv_bfloat162 h1 = __floats2bfloat162_rn(v.z, v.w);
        float2 f0 = __bfloat1622float2(h0);
        float2 f1 = __bfloat1622float2(h1);
        __nv_bfloat162 l0 = __floats2bfloat162_rn(v.x - f0.x, v.y - f0.y);
        __nv_bfloat162 l1 = __floats2bfloat162_rn(v.z - f1.x, v.w - f1.y);
        uint2 hu, lu;
        hu.x = *reinterpret_cast<uint32_t*>(&h0);
        hu.y = *reinterpret_cast<uint32_t*>(&h1);
        lu.x = *reinterpret_cast<uint32_t*>(&l0);
        lu.y = *reinterpret_cast<uint32_t*>(&l1);
        hrow[e4] = hu;
        lrow[e4] = lu;
    }
#pragma unroll
    for (int o = 16; o > 0; o >>= 1) ss += __shfl_xor_sync(0xffffffffu, ss, o);
    if (lane == 0) g_tinv[w] = 1.f / fmaxf(sqrtf(ss), EPS_F);
}

// ---------------- bf16x3 HMMA GEMM: out[M,512] = (Ahi+Alo)(Bhi+Blo)^T * tinv ----------------
// CTA tile 128x128, 8 warps (4 m x 2 n), warp tile 32x64, K-chunk 64, 3-stage pipeline.
#define MT   128
#define NT   128
#define KC   64
#define NC   (DDIM / KC)             // 16
#define OFF_AHI  0
#define OFF_ALO  16384
#define OFF_BHI  32768
#define OFF_BLO  49152
#define STAGE    65536
#define NSTAGE   3
#define SMEM_BYTES (NSTAGE * STAGE + 1024)

__device__ __forceinline__ void load_chunk(uint32_t stage, int m0, int n0, int gk0, int tid) {
#pragma unroll
    for (int p = 0; p < 4; p++) {
        int i = tid + p * 256;
        int row = i >> 3, c16 = i & 7;
        uint32_t off = SWZ((uint32_t)row * 128 + (uint32_t)c16 * 16);
        const char* sh = (const char*)(g_ahi + (size_t)(m0 + row) * DDIM + gk0) + c16 * 16;
        const char* sl = (const char*)(g_alo + (size_t)(m0 + row) * DDIM + gk0) + c16 * 16;
        CP_ASYNC16(stage + OFF_AHI + off, sh);
        CP_ASYNC16(stage + OFF_ALO + off, sl);
    }
#pragma unroll
    for (int p = 0; p < 4; p++) {
        int i = tid + p * 256;
        int row = i >> 3, c16 = i & 7;
        uint32_t off = SWZ((uint32_t)row * 128 + (uint32_t)c16 * 16);
        const char* sh = (const char*)(g_bhi + (size_t)(n0 + row) * DDIM + gk0) + c16 * 16;
        const char* sl = (const char*)(g_blo + (size_t)(n0 + row) * DDIM + gk0) + c16 * 16;
        CP_ASYNC16(stage + OFF_BHI + off, sh);
        CP_ASYNC16(stage + OFF_BLO + off, sl);
    }
    CP_COMMIT();
}

__global__ void __launch_bounds__(256, 1) gemm_mma_kernel(float* __restrict__ out) {
    extern __shared__ char dsm[];
    uint32_t sb = (smem_u32(dsm) + 1023) & ~1023u;

    const int tid  = threadIdx.x;
    const int wid  = tid >> 5;
    const int lane = tid & 31;
    const int wm   = wid >> 1;            // 0..3 (m)
    const int wn   = wid & 1;             // 0..1 (n)
    const int n0 = blockIdx.x * NT;
    const int m0 = blockIdx.y * MT;

    float acc[2][8][4];
#pragma unroll
    for (int a = 0; a < 2; a++)
#pragma unroll
        for (int b = 0; b < 8; b++)
#pragma unroll
            for (int c = 0; c < 4; c++) acc[a][b][c] = 0.f;

    // prologue: 2 chunks in flight
    load_chunk(sb + 0 * STAGE, m0, n0, 0, tid);
    load_chunk(sb + 1 * STAGE, m0, n0, KC, tid);

    // precomputed lane pieces
    const int a_r  = (lane & 15);             // row within 16
    const int a_kh = (lane >> 4);             // k half
    const int b_r  = (lane & 7) + ((lane >> 4) << 3);
    const int b_kh = (lane >> 3) & 1;

    int stg = 0;                              // stage index of chunk c
    for (int c = 0; c < NC; c++) {
        if (c < NC - 1) CP_WAIT(1); else CP_WAIT(0);
        __syncthreads();                      // all warps done with chunk c-1; chunk c visible
        uint32_t stage = sb + (uint32_t)stg * STAGE;

#pragma unroll
        for (int k16 = 0; k16 < 4; k16++) {
            uint32_t ah[2][4], al[2][4], bh[4][4], bl[4][4];
#pragma unroll
            for (int mt = 0; mt < 2; mt++) {
                int row = wm * 32 + mt * 16 + a_r;
                uint32_t c16 = (uint32_t)((k16 * 2 + a_kh) ^ (row & 7));
                uint32_t off = (uint32_t)row * 128 + c16 * 16;
                ldsm_x4(ah[mt], stage + OFF_AHI + off);
                ldsm_x4(al[mt], stage + OFF_ALO + off);
            }
#pragma unroll
            for (int nt = 0; nt < 4; nt++) {
                int row = wn * 64 + nt * 16 + b_r;
                uint32_t c16 = (uint32_t)((k16 * 2 + b_kh) ^ (row & 7));
                uint32_t off = (uint32_t)row * 128 + c16 * 16;
                ldsm_x4(bh[nt], stage + OFF_BHI + off);
                ldsm_x4(bl[nt], stage + OFF_BLO + off);
            }
            // pass 1: hi*hi — 16 independent MMAs (acc reuse distance = 16)
#pragma unroll
            for (int mt = 0; mt < 2; mt++)
#pragma unroll
                for (int nt = 0; nt < 4; nt++) {
                    mma16816(acc[mt][nt * 2 + 0], ah[mt], &bh[nt][0]);
                    mma16816(acc[mt][nt * 2 + 1], ah[mt], &bh[nt][2]);
                }
            // pass 2: lo*hi
#pragma unroll
            for (int mt = 0; mt < 2; mt++)
#pragma unroll
                for (int nt = 0; nt < 4; nt++) {
                    mma16816(acc[mt][nt * 2 + 0], al[mt], &bh[nt][0]);
                    mma16816(acc[mt][nt * 2 + 1], al[mt], &bh[nt][2]);
                }
            // pass 3: hi*lo
#pragma unroll
            for (int mt = 0; mt < 2; mt++)
#pragma unroll
                for (int nt = 0; nt < 4; nt++) {
                    mma16816(acc[mt][nt * 2 + 0], ah[mt], &bl[nt][0]);
                    mma16816(acc[mt][nt * 2 + 1], ah[mt], &bl[nt][2]);
                }
        }

        // load chunk c+2 into the stage that held chunk c-1 (all threads are past it)
        if (c + 2 < NC) {
            int nstg = stg + 2; if (nstg >= NSTAGE) nstg -= NSTAGE;
            load_chunk(sb + (uint32_t)nstg * STAGE, m0, n0, (c + 2) * KC, tid);
        }
        if (++stg == NSTAGE) stg = 0;
    }

    // epilogue: scale by 1/||t|| and store
    const int qrow = lane >> 2;
    const int qcol = (lane & 3) * 2;
#pragma unroll
    for (int mt = 0; mt < 2; mt++) {
        int r0 = m0 + wm * 32 + mt * 16 + qrow;
        int r1 = r0 + 8;
        float t0 = g_tinv[r0], t1 = g_tinv[r1];
        float* p0 = out + (size_t)r0 * C_CLASSES + n0 + wn * 64 + qcol;
        float* p1 = out + (size_t)r1 * C_CLASSES + n0 + wn * 64 + qcol;
#pragma unroll
        for (int nf = 0; nf < 8; nf++) {
            float2 v0, v1;
            v0.x = acc[mt][nf][0] * t0; v0.y = acc[mt][nf][1] * t0;
            v1.x = acc[mt][nf][2] * t1; v1.y = acc[mt][nf][3] * t1;
            *(float2*)(p0 + nf * 8) = v0;
            *(float2*)(p1 + nf * 8) = v1;
        }
    }
}

// ---------------- launch ----------------
extern "C" void kernel_launch(void* const* d_in, const int* in_sizes, int n_in,
                              void* d_out, int out_size) {
    const float* ctx    = (const float*)d_in[0];
    const int*   labels = (const int*)d_in[1];
    const float* tgt    = (const float*)d_in[2];
    const int n_ctx = in_sizes[1];
    const int n_tgt = in_sizes[2] / DDIM;

    float* logits    = (float*)d_out;
    float* means_out = (float*)d_out + (size_t)n_tgt * C_CLASSES;

    cudaFuncSetAttribute(gemm_mma_kernel, cudaFuncAttributeMaxDynamicSharedMemorySize, SMEM_BYTES);

    zero_kernel<<<1, C_CLASSES>>>();
    count_kernel<<<64, 256>>>(labels, n_ctx);
    scan_kernel<<<1, C_CLASSES>>>();
    scatter_kernel<<<(n_ctx + 255) / 256, 256>>>(labels, n_ctx);
    classsum_kernel<<<dim3(C_CLASSES, DDIM / 256), 256>>>(ctx);
    finalize_kernel<<<C_CLASSES, 256>>>(means_out);
    split_tinv_kernel<<<(n_tgt + 7) / 8, 256>>>((const float4*)tgt, n_tgt);
    gemm_mma_kernel<<<dim3(C_CLASSES / NT, n_tgt / MT), 256, SMEM_BYTES>>>(logits);
}